// round 7
// baseline (speedup 1.0000x reference)
#include <cuda_runtime.h>
#include <cuda_fp16.h>
#include <math_constants.h>
#include <cstdint>

// Problem constants
#define S_LEN   2048
#define EMB     1024
#define NHEAD   16
#define HDIM    64
#define BATCH   4
#define MTOT    (BATCH * S_LEN)        // 8192
#define E3      (3 * EMB)              // 3072

// Scratch (device globals — no allocations allowed)
__device__ __half g_hx [(size_t)MTOT * EMB];   // x in fp16
__device__ __half g_hw1[(size_t)E3 * EMB];     // W_qkv in fp16
__device__ __half g_hw2[(size_t)EMB * EMB];    // W_proj in fp16
__device__ __half g_qkv[(size_t)MTOT * E3];    // qkv (half)
__device__ __half g_att[(size_t)MTOT * EMB];   // attention out (half)

// ===========================================================================
// helpers
// ===========================================================================
__device__ __forceinline__ uint32_t smem_u32(const void* p) {
    uint32_t a;
    asm("{ .reg .u64 t; cvta.to.shared.u64 t, %1; cvt.u32.u64 %0, t; }"
        : "=r"(a) : "l"(p));
    return a;
}

__device__ __forceinline__ void mma_f16(float* d, const uint32_t* a,
                                        uint32_t b0, uint32_t b1) {
    asm volatile(
        "mma.sync.aligned.m16n8k16.row.col.f32.f16.f16.f32 "
        "{%0,%1,%2,%3}, {%4,%5,%6,%7}, {%8,%9}, {%0,%1,%2,%3};"
        : "+f"(d[0]), "+f"(d[1]), "+f"(d[2]), "+f"(d[3])
        : "r"(a[0]), "r"(a[1]), "r"(a[2]), "r"(a[3]), "r"(b0), "r"(b1));
}

#define LDM_X4(r, addr) \
    asm volatile("ldmatrix.sync.aligned.m8n8.x4.shared.b16 {%0,%1,%2,%3}, [%4];" \
        : "=r"((r)[0]), "=r"((r)[1]), "=r"((r)[2]), "=r"((r)[3]) : "r"(addr))
#define LDM_X4_T(r, addr) \
    asm volatile("ldmatrix.sync.aligned.m8n8.x4.trans.shared.b16 {%0,%1,%2,%3}, [%4];" \
        : "=r"((r)[0]), "=r"((r)[1]), "=r"((r)[2]), "=r"((r)[3]) : "r"(addr))

#define CP_ASYNC16(dst_u32, src_ptr) \
    asm volatile("cp.async.cg.shared.global [%0], [%1], 16;" \
                 :: "r"(dst_u32), "l"(src_ptr))
#define CP_COMMIT()  asm volatile("cp.async.commit_group;" ::: "memory")
#define CP_WAIT0()   asm volatile("cp.async.wait_group 0;" ::: "memory")
#define CP_WAIT2()   asm volatile("cp.async.wait_group 2;" ::: "memory")

__device__ __forceinline__ uint32_t h2u(__half2 h) {
    return *reinterpret_cast<uint32_t*>(&h);
}

// ===========================================================================
// fp32 -> fp16 conversion (n multiple of 8)
// ===========================================================================
__global__ __launch_bounds__(256) void f32_to_f16(
    const float* __restrict__ s, __half* __restrict__ d, int n)
{
    int i = (blockIdx.x * blockDim.x + threadIdx.x) * 8;
    if (i < n) {
        float4 v0 = *(const float4*)(s + i);
        float4 v1 = *(const float4*)(s + i + 4);
        uint4 o;
        o.x = h2u(__float22half2_rn(make_float2(v0.x, v0.y)));
        o.y = h2u(__float22half2_rn(make_float2(v0.z, v0.w)));
        o.z = h2u(__float22half2_rn(make_float2(v1.x, v1.y)));
        o.w = h2u(__float22half2_rn(make_float2(v1.z, v1.w)));
        *(uint4*)(d + i) = o;
    }
}

// ===========================================================================
// fp16 mma.sync GEMM (NT), 4-stage cp.async pipeline.
// CTA 128x128, BK=32 halfs, 256 threads = 8 warps (warp 64x32), m16n8k16.
// smem stage: A[128 rows x 80B] + B[128 x 80B] = 20480 B; 4 stages = 80 KB.
// Row stride 80B -> ldmatrix chunk index r*5 mod 8 is a permutation: conflict-free.
// Requires M%128==0, N%128==0, K%32==0, K/32 >= 3.
// ===========================================================================
#define GASTG 10240
#define GSTG  20480
#define GEMM_SMEM (4 * GSTG)   // 81920

template<int HALF_OUT>
__global__ __launch_bounds__(256, 2) void gemm_f16_nt_bias(
    const __half* __restrict__ A, const __half* __restrict__ B,
    const float* __restrict__ bias, void* __restrict__ Cv,
    int M, int N, int K)
{
    extern __shared__ __half smh[];
    const uint32_t sb = smem_u32(smh);

    const int tid  = threadIdx.x;
    const int wid  = tid >> 5;
    const int lane = tid & 31;
    const int g    = lane >> 2;
    const int t    = lane & 3;
    const int wm   = (wid & 1) * 64;
    const int wn   = (wid >> 1) * 32;
    const int bm   = blockIdx.y * 128;
    const int bn   = blockIdx.x * 128;

    // loader: 2 x 16B chunks per thread per matrix-stage
    const int lrow = tid >> 2;            // 0..63 (+64)
    const int lch  = tid & 3;             // 16B chunk (8 halfs)
    const __half* Arow = A + (size_t)(bm + lrow) * K + lch * 8;
    const __half* Brow = B + (size_t)(bn + lrow) * K + lch * 8;
    const uint32_t st0 = (uint32_t)(lrow * 80 + lch * 16);
    const uint32_t st1 = st0 + 64 * 80;

    // ldmatrix per-lane bases (bytes within a stage)
    const uint32_t a_lm =
        (uint32_t)(((wm + ((lane >> 3) & 1) * 8 + (lane & 7)) * 80 +
                    ((lane >> 4) & 1) * 16));
    const uint32_t b_lm = GASTG +
        (uint32_t)(((wn + ((lane >> 4) & 1) * 8 + (lane & 7)) * 80 +
                    ((lane >> 3) & 1) * 16));

    float bias0[4], bias1[4];
#pragma unroll
    for (int nt = 0; nt < 4; nt++) {
        int c = bn + wn + nt * 8 + 2 * t;
        bias0[nt] = bias[c];
        bias1[nt] = bias[c + 1];
    }

    float acc[4][4][4];
#pragma unroll
    for (int mt = 0; mt < 4; mt++)
#pragma unroll
        for (int nt = 0; nt < 4; nt++)
#pragma unroll
            for (int r = 0; r < 4; r++) acc[mt][nt][r] = 0.0f;

    const int nk = K / 32;

    // prologue: prefetch stages 0..2 (one commit group per stage)
#pragma unroll
    for (int s = 0; s < 3; s++) {
        const uint32_t dst = sb + (uint32_t)s * GSTG;
        const int ko = s * 32;
        CP_ASYNC16(dst + st0,         Arow + ko);
        CP_ASYNC16(dst + st1,         Arow + (size_t)64 * K + ko);
        CP_ASYNC16(dst + GASTG + st0, Brow + ko);
        CP_ASYNC16(dst + GASTG + st1, Brow + (size_t)64 * K + ko);
        CP_COMMIT();
    }

    for (int kt = 0; kt < nk; kt++) {
        const int slot = kt & 3;
        CP_WAIT2();              // stage kt complete (one group per iter)
        __syncthreads();

        if (kt + 3 < nk) {
            const uint32_t dst = sb + (uint32_t)((kt + 3) & 3) * GSTG;
            const int ko = (kt + 3) * 32;
            CP_ASYNC16(dst + st0,         Arow + ko);
            CP_ASYNC16(dst + st1,         Arow + (size_t)64 * K + ko);
            CP_ASYNC16(dst + GASTG + st0, Brow + ko);
            CP_ASYNC16(dst + GASTG + st1, Brow + (size_t)64 * K + ko);
        }
        CP_COMMIT();             // unconditional: keep group accounting aligned

        const uint32_t aB = sb + (uint32_t)slot * GSTG + a_lm;
        const uint32_t bB = sb + (uint32_t)slot * GSTG + b_lm;
#pragma unroll
        for (int c = 0; c < 2; c++) {         // k chunk of 16 halfs
            uint32_t af[4][4], bfr[2][4];
#pragma unroll
            for (int mt = 0; mt < 4; mt++)
                LDM_X4(af[mt], aB + mt * 1280 + c * 32);
#pragma unroll
            for (int ntp = 0; ntp < 2; ntp++)
                LDM_X4(bfr[ntp], bB + ntp * 1280 + c * 32);
#pragma unroll
            for (int mt = 0; mt < 4; mt++)
#pragma unroll
                for (int nt = 0; nt < 4; nt++)
                    mma_f16(acc[mt][nt], af[mt],
                            bfr[nt >> 1][(nt & 1) * 2],
                            bfr[nt >> 1][(nt & 1) * 2 + 1]);
        }
    }

    // epilogue
#pragma unroll
    for (int mt = 0; mt < 4; mt++) {
        const int r0 = bm + wm + mt * 16 + g;
#pragma unroll
        for (int nt = 0; nt < 4; nt++) {
            const int c0 = bn + wn + nt * 8 + 2 * t;
            float v0 = acc[mt][nt][0] + bias0[nt];
            float v1 = acc[mt][nt][1] + bias1[nt];
            float v2 = acc[mt][nt][2] + bias0[nt];
            float v3 = acc[mt][nt][3] + bias1[nt];
            if (HALF_OUT) {
                __half* Ch = (__half*)Cv;
                *(__half2*)(Ch + (size_t)r0 * N + c0) =
                    __float22half2_rn(make_float2(v0, v1));
                *(__half2*)(Ch + (size_t)(r0 + 8) * N + c0) =
                    __float22half2_rn(make_float2(v2, v3));
            } else {
                float* Cf = (float*)Cv;
                *(float2*)(Cf + (size_t)r0 * N + c0)       = make_float2(v0, v1);
                *(float2*)(Cf + (size_t)(r0 + 8) * N + c0) = make_float2(v2, v3);
            }
        }
    }
}

// ===========================================================================
// fp16 tensor-core causal flash attention.
// Block = (q-tile 128, head, batch), 256 threads = 8 warps, warp = 16 q-rows.
// Q frags in regs; K ldmatrix; V ldmatrix.trans; P in registers.
// KV tiles of 64 rows, double-buffered cp.async. exp2-domain softmax.
// Per-warp skip of fully-masked tiles.
// smem: Q 128x144B = 18432; K,V 2 stages of 64x144B = 9216 each. Total 55296.
// ===========================================================================
#define AQ    18432
#define AST   9216
#define ATTN_SMEM (AQ + 4 * AST)    // 55296

__global__ __launch_bounds__(256, 2) void attn_f16_kernel(
    const __half* __restrict__ qkv, __half* __restrict__ out)
{
    extern __shared__ __half smh[];
    const uint32_t sb = smem_u32(smh);
    // bytes: Q [0,AQ), K stage s at AQ + s*AST, V stage s at AQ+2*AST + s*AST

    const int qt2  = blockIdx.x;          // q tile of 128 (0..15)
    const int h    = blockIdx.y;
    const int b    = blockIdx.z;
    const int tid  = threadIdx.x;
    const int wid  = tid >> 5;
    const int lane = tid & 31;
    const int g    = lane >> 2;
    const int t    = lane & 3;
    const int r0   = wid * 16;            // warp q-row base within 128-tile
    const float sl2e = 0.125f * 1.4426950408889634f;  // scale * log2(e)

    // loader mapping
    const int lrow = tid >> 3;            // 0..31
    const int lch  = tid & 7;
    const uint32_t qst = (uint32_t)(lrow * 144 + lch * 16);
    const uint32_t kst = (uint32_t)(lrow * 144 + lch * 16);

    const size_t bq = ((size_t)b * S_LEN + (size_t)qt2 * 128);
    const __half* Qg = qkv + (bq + lrow) * E3 + h * HDIM + lch * 8;

    // ldmatrix per-lane bases (bytes, stage-relative)
    const uint32_t k_lm = sb + AQ +
        (uint32_t)(((((lane >> 4) & 1) * 8 + (lane & 7)) * 144 +
                    ((lane >> 3) & 1) * 16));
    const uint32_t v_lm = sb + AQ + 2 * AST +
        (uint32_t)(((((lane >> 3) & 1) * 8 + (lane & 7)) * 144 +
                    ((lane >> 4) & 1) * 16));

    // prologue: load Q (4 chunks), K0, V0 (2 chunks each)
    {
        const size_t bk = (size_t)b * S_LEN;
        const __half* Kg = qkv + (bk + lrow) * E3 + EMB + h * HDIM + lch * 8;
        const __half* Vg = Kg + EMB;
#pragma unroll
        for (int i = 0; i < 4; i++)
            CP_ASYNC16(sb + qst + i * (32 * 144), Qg + (size_t)(i * 32) * E3);
#pragma unroll
        for (int i = 0; i < 2; i++) {
            CP_ASYNC16(sb + AQ + kst + i * (32 * 144),
                       Kg + (size_t)(i * 32) * E3);
            CP_ASYNC16(sb + AQ + 2 * AST + kst + i * (32 * 144),
                       Vg + (size_t)(i * 32) * E3);
        }
        CP_COMMIT();
        CP_WAIT0();
        __syncthreads();
    }

    // Q fragments (plain LDS, stride 36 words: bank = 4g+t, conflict-free)
    const uint32_t* Qw = (const uint32_t*)smh;
    uint32_t qf[4][4];
#pragma unroll
    for (int c = 0; c < 4; c++) {
        const uint32_t* p0 = Qw + (r0 + g) * 36 + c * 8 + t;
        const uint32_t* p1 = Qw + (r0 + g + 8) * 36 + c * 8 + t;
        qf[c][0] = p0[0];
        qf[c][1] = p1[0];
        qf[c][2] = p0[4];
        qf[c][3] = p1[4];
    }

    float m_lo = -CUDART_INF_F, m_hi = -CUDART_INF_F;
    float l_lo = 0.0f, l_hi = 0.0f;
    float oacc[8][4];
#pragma unroll
    for (int nt = 0; nt < 8; nt++)
#pragma unroll
        for (int r = 0; r < 4; r++) oacc[nt][r] = 0.0f;

    const int ktmax = 2 * qt2 + 1;
    const int wrow_lo = qt2 * 128 + r0;     // warp min global q-row
    const int wrow_hi = wrow_lo + 15;       // warp max global q-row

    for (int kt = 0; kt <= ktmax; kt++) {
        const int cur  = kt & 1;
        const bool more = (kt < ktmax);

        // prefetch next K/V tile
        if (more) {
            const int nxt = cur ^ 1;
            const size_t bk = (size_t)b * S_LEN + (size_t)(kt + 1) * 64;
            const __half* Kg = qkv + (bk + lrow) * E3 + EMB + h * HDIM + lch * 8;
            const __half* Vg = Kg + EMB;
            const uint32_t dK = sb + AQ + (uint32_t)nxt * AST;
            const uint32_t dV = sb + AQ + 2 * AST + (uint32_t)nxt * AST;
#pragma unroll
            for (int i = 0; i < 2; i++) {
                CP_ASYNC16(dK + kst + i * (32 * 144), Kg + (size_t)(i * 32) * E3);
                CP_ASYNC16(dV + kst + i * (32 * 144), Vg + (size_t)(i * 32) * E3);
            }
            CP_COMMIT();
        }

        // per-warp skip: tile entirely above the causal boundary for this warp
        if (kt * 64 <= wrow_hi) {
            // ---- S = Q K^T (16x64 per warp) ----
            const uint32_t kB = k_lm + (uint32_t)cur * AST;
            float sacc[8][4];
#pragma unroll
            for (int nt = 0; nt < 8; nt++)
#pragma unroll
                for (int r = 0; r < 4; r++) sacc[nt][r] = 0.0f;

#pragma unroll
            for (int c = 0; c < 4; c++) {
#pragma unroll
                for (int ntp = 0; ntp < 4; ntp++) {
                    uint32_t bfr[4];
                    LDM_X4(bfr, kB + ntp * 2304 + c * 32);
                    mma_f16(sacc[2 * ntp + 0], qf[c], bfr[0], bfr[1]);
                    mma_f16(sacc[2 * ntp + 1], qf[c], bfr[2], bfr[3]);
                }
            }

            // ---- scale into log2 domain + causal mask ----
            const bool needmask = (kt * 64 + 63 > wrow_lo);
#pragma unroll
            for (int nt = 0; nt < 8; nt++) {
#pragma unroll
                for (int r = 0; r < 4; r++) sacc[nt][r] *= sl2e;
                if (needmask) {
                    const int c0 = kt * 64 + nt * 8 + 2 * t;
                    const int rlo = wrow_lo + g, rhi = rlo + 8;
                    if (c0 + 0 > rlo) sacc[nt][0] = -CUDART_INF_F;
                    if (c0 + 1 > rlo) sacc[nt][1] = -CUDART_INF_F;
                    if (c0 + 0 > rhi) sacc[nt][2] = -CUDART_INF_F;
                    if (c0 + 1 > rhi) sacc[nt][3] = -CUDART_INF_F;
                }
            }

            // ---- online softmax (exp2 domain, quad shuffles) ----
            float tmax_lo = -CUDART_INF_F, tmax_hi = -CUDART_INF_F;
#pragma unroll
            for (int nt = 0; nt < 8; nt++) {
                tmax_lo = fmaxf(tmax_lo, fmaxf(sacc[nt][0], sacc[nt][1]));
                tmax_hi = fmaxf(tmax_hi, fmaxf(sacc[nt][2], sacc[nt][3]));
            }
            tmax_lo = fmaxf(tmax_lo, __shfl_xor_sync(0xFFFFFFFF, tmax_lo, 1));
            tmax_lo = fmaxf(tmax_lo, __shfl_xor_sync(0xFFFFFFFF, tmax_lo, 2));
            tmax_hi = fmaxf(tmax_hi, __shfl_xor_sync(0xFFFFFFFF, tmax_hi, 1));
            tmax_hi = fmaxf(tmax_hi, __shfl_xor_sync(0xFFFFFFFF, tmax_hi, 2));

            const float mnew_lo = fmaxf(m_lo, tmax_lo);
            const float mnew_hi = fmaxf(m_hi, tmax_hi);
            const float alpha_lo = exp2f(m_lo - mnew_lo);
            const float alpha_hi = exp2f(m_hi - mnew_hi);

            float sum_lo = 0.0f, sum_hi = 0.0f;
            uint32_t pa[8][2];
#pragma unroll
            for (int nt = 0; nt < 8; nt++) {
                float p0 = exp2f(sacc[nt][0] - mnew_lo);
                float p1 = exp2f(sacc[nt][1] - mnew_lo);
                float p2 = exp2f(sacc[nt][2] - mnew_hi);
                float p3 = exp2f(sacc[nt][3] - mnew_hi);
                sum_lo += p0 + p1;
                sum_hi += p2 + p3;
                pa[nt][0] = h2u(__float22half2_rn(make_float2(p0, p1)));
                pa[nt][1] = h2u(__float22half2_rn(make_float2(p2, p3)));
            }
            sum_lo += __shfl_xor_sync(0xFFFFFFFF, sum_lo, 1);
            sum_lo += __shfl_xor_sync(0xFFFFFFFF, sum_lo, 2);
            sum_hi += __shfl_xor_sync(0xFFFFFFFF, sum_hi, 1);
            sum_hi += __shfl_xor_sync(0xFFFFFFFF, sum_hi, 2);

            l_lo = l_lo * alpha_lo + sum_lo;
            l_hi = l_hi * alpha_hi + sum_hi;
            m_lo = mnew_lo;
            m_hi = mnew_hi;

#pragma unroll
            for (int nt = 0; nt < 8; nt++) {
                oacc[nt][0] *= alpha_lo;
                oacc[nt][1] *= alpha_lo;
                oacc[nt][2] *= alpha_hi;
                oacc[nt][3] *= alpha_hi;
            }

            // ---- O += P V ----
            const uint32_t vB = v_lm + (uint32_t)cur * AST;
#pragma unroll
            for (int c = 0; c < 4; c++) {
                uint32_t af[4] = { pa[2 * c][0], pa[2 * c][1],
                                   pa[2 * c + 1][0], pa[2 * c + 1][1] };
#pragma unroll
                for (int ntp = 0; ntp < 4; ntp++) {
                    uint32_t bfr[4];
                    LDM_X4_T(bfr, vB + c * 2304 + ntp * 32);
                    mma_f16(oacc[2 * ntp + 0], af, bfr[0], bfr[1]);
                    mma_f16(oacc[2 * ntp + 1], af, bfr[2], bfr[3]);
                }
            }
        }

        if (more) {
            CP_WAIT0();
            __syncthreads();
        }
    }

    // ---- epilogue: normalize + store half ----
    const float inv_lo = 1.0f / l_lo;
    const float inv_hi = 1.0f / l_hi;
    __half* obase = out + bq * EMB + h * HDIM;
    __half* orow0 = obase + (size_t)(r0 + g) * EMB;
    __half* orow1 = obase + (size_t)(r0 + g + 8) * EMB;
#pragma unroll
    for (int nt = 0; nt < 8; nt++) {
        const int c0 = nt * 8 + 2 * t;
        *(__half2*)(orow0 + c0) = __float22half2_rn(
            make_float2(oacc[nt][0] * inv_lo, oacc[nt][1] * inv_lo));
        *(__half2*)(orow1 + c0) = __float22half2_rn(
            make_float2(oacc[nt][2] * inv_hi, oacc[nt][3] * inv_hi));
    }
}

// ===========================================================================
// Launch
// ===========================================================================
extern "C" void kernel_launch(void* const* d_in, const int* in_sizes, int n_in,
                              void* d_out, int out_size)
{
    const float* x     = (const float*)d_in[0];   // [4,2048,1024]
    const float* Wqkv  = (const float*)d_in[1];   // [3072,1024]
    const float* bqkv  = (const float*)d_in[2];   // [3072]
    const float* Wproj = (const float*)d_in[3];   // [1024,1024]
    const float* bproj = (const float*)d_in[4];   // [1024]
    float* out = (float*)d_out;                   // [4,2048,1024]

    __half *hx, *hw1, *hw2, *qkv, *att;
    cudaGetSymbolAddress((void**)&hx,  g_hx);
    cudaGetSymbolAddress((void**)&hw1, g_hw1);
    cudaGetSymbolAddress((void**)&hw2, g_hw2);
    cudaGetSymbolAddress((void**)&qkv, g_qkv);
    cudaGetSymbolAddress((void**)&att, g_att);

    cudaFuncSetAttribute(gemm_f16_nt_bias<1>,
                         cudaFuncAttributeMaxDynamicSharedMemorySize, GEMM_SMEM);
    cudaFuncSetAttribute(gemm_f16_nt_bias<0>,
                         cudaFuncAttributeMaxDynamicSharedMemorySize, GEMM_SMEM);
    cudaFuncSetAttribute(attn_f16_kernel,
                         cudaFuncAttributeMaxDynamicSharedMemorySize, ATTN_SMEM);

    // 0) fp32 -> fp16 conversions
    f32_to_f16<<<(MTOT * EMB / 8 + 255) / 256, 256>>>(x, hx, MTOT * EMB);
    f32_to_f16<<<(E3 * EMB / 8 + 255) / 256, 256>>>(Wqkv, hw1, E3 * EMB);
    f32_to_f16<<<(EMB * EMB / 8 + 255) / 256, 256>>>(Wproj, hw2, EMB * EMB);

    // 1) QKV GEMM (fp16 mma, half out)
    {
        dim3 grid(E3 / 128, MTOT / 128);
        gemm_f16_nt_bias<1><<<grid, 256, GEMM_SMEM>>>(hx, hw1, bqkv, qkv,
                                                      MTOT, E3, EMB);
    }
    // 2) causal flash attention (fp16 tensor cores) -> g_att (half)
    {
        dim3 grid(S_LEN / 128, NHEAD, BATCH);
        attn_f16_kernel<<<grid, 256, ATTN_SMEM>>>(qkv, att);
    }
    // 3) proj GEMM (fp16 mma, float out)
    {
        dim3 grid(EMB / 128, MTOT / 128);
        gemm_f16_nt_bias<0><<<grid, 256, GEMM_SMEM>>>(att, hw2, bproj, out,
                                                      MTOT, EMB, EMB);
    }
}

// round 8
// speedup vs baseline: 1.0838x; 1.0838x over previous
#include <cuda_runtime.h>
#include <cuda_fp16.h>
#include <math_constants.h>
#include <cstdint>

// Problem constants
#define S_LEN   2048
#define EMB     1024
#define NHEAD   16
#define HDIM    64
#define BATCH   4
#define MTOT    (BATCH * S_LEN)        // 8192
#define E3      (3 * EMB)              // 3072

// Scratch (device globals — no allocations allowed)
__device__ __half g_hx [(size_t)MTOT * EMB];   // x in fp16
__device__ __half g_hw1[(size_t)E3 * EMB];     // W_qkv in fp16
__device__ __half g_hw2[(size_t)EMB * EMB];    // W_proj in fp16
__device__ __half g_qkv[(size_t)MTOT * E3];    // qkv (half)
__device__ __half g_att[(size_t)MTOT * EMB];   // attention out (half)

// ===========================================================================
// helpers
// ===========================================================================
__device__ __forceinline__ uint32_t smem_u32(const void* p) {
    uint32_t a;
    asm("{ .reg .u64 t; cvta.to.shared.u64 t, %1; cvt.u32.u64 %0, t; }"
        : "=r"(a) : "l"(p));
    return a;
}

__device__ __forceinline__ void mma_f16(float* d, const uint32_t* a,
                                        uint32_t b0, uint32_t b1) {
    asm volatile(
        "mma.sync.aligned.m16n8k16.row.col.f32.f16.f16.f32 "
        "{%0,%1,%2,%3}, {%4,%5,%6,%7}, {%8,%9}, {%0,%1,%2,%3};"
        : "+f"(d[0]), "+f"(d[1]), "+f"(d[2]), "+f"(d[3])
        : "r"(a[0]), "r"(a[1]), "r"(a[2]), "r"(a[3]), "r"(b0), "r"(b1));
}

#define LDM_X4(r, addr) \
    asm volatile("ldmatrix.sync.aligned.m8n8.x4.shared.b16 {%0,%1,%2,%3}, [%4];" \
        : "=r"((r)[0]), "=r"((r)[1]), "=r"((r)[2]), "=r"((r)[3]) : "r"(addr))
#define LDM_X4_T(r, addr) \
    asm volatile("ldmatrix.sync.aligned.m8n8.x4.trans.shared.b16 {%0,%1,%2,%3}, [%4];" \
        : "=r"((r)[0]), "=r"((r)[1]), "=r"((r)[2]), "=r"((r)[3]) : "r"(addr))

#define CP_ASYNC16(dst_u32, src_ptr) \
    asm volatile("cp.async.cg.shared.global [%0], [%1], 16;" \
                 :: "r"(dst_u32), "l"(src_ptr))
#define CP_COMMIT()  asm volatile("cp.async.commit_group;" ::: "memory")
#define CP_WAIT0()   asm volatile("cp.async.wait_group 0;" ::: "memory")
#define CP_WAIT1()   asm volatile("cp.async.wait_group 1;" ::: "memory")

__device__ __forceinline__ uint32_t h2u(__half2 h) {
    return *reinterpret_cast<uint32_t*>(&h);
}

// ===========================================================================
// fp32 -> fp16 conversion (n multiple of 8)
// ===========================================================================
__global__ __launch_bounds__(256) void f32_to_f16(
    const float* __restrict__ s, __half* __restrict__ d, int n)
{
    int i = (blockIdx.x * blockDim.x + threadIdx.x) * 8;
    if (i < n) {
        float4 v0 = *(const float4*)(s + i);
        float4 v1 = *(const float4*)(s + i + 4);
        uint4 o;
        o.x = h2u(__float22half2_rn(make_float2(v0.x, v0.y)));
        o.y = h2u(__float22half2_rn(make_float2(v0.z, v0.w)));
        o.z = h2u(__float22half2_rn(make_float2(v1.x, v1.y)));
        o.w = h2u(__float22half2_rn(make_float2(v1.z, v1.w)));
        *(uint4*)(d + i) = o;
    }
}

// ===========================================================================
// fp16 mma.sync GEMM (NT), 3-stage cp.async pipeline, BK=64.
// CTA 128x128, 256 threads = 8 warps (warp 64x32), m16n8k16, ldmatrix.
// smem: row stride 144B. Stage = 128*144 = 18432 B per matrix.
// A stages at s*GST, B stages at 3*GST + s*GST. Total 6*GST = 110592 B.
// Requires M%128==0, N%128==0, K%64==0, K/64 >= 2.
// ===========================================================================
#define GST   18432
#define GEMM_SMEM (6 * GST)    // 110592

template<int HALF_OUT>
__global__ __launch_bounds__(256, 2) void gemm_f16_nt_bias(
    const __half* __restrict__ A, const __half* __restrict__ B,
    const float* __restrict__ bias, void* __restrict__ Cv,
    int M, int N, int K)
{
    extern __shared__ __half smh[];
    const uint32_t sb = smem_u32(smh);

    const int tid  = threadIdx.x;
    const int wid  = tid >> 5;
    const int lane = tid & 31;
    const int g    = lane >> 2;
    const int t    = lane & 3;
    const int wm   = (wid & 1) * 64;
    const int wn   = (wid >> 1) * 32;
    const int bm   = blockIdx.y * 128;
    const int bn   = blockIdx.x * 128;

    // loader: 4 x 16B chunks per thread per matrix-stage
    const int lrow = tid >> 3;            // + i*32
    const int lch  = tid & 7;
    const __half* Arow = A + (size_t)(bm + lrow) * K + lch * 8;
    const __half* Brow = B + (size_t)(bn + lrow) * K + lch * 8;
    uint32_t ldst[4];
#pragma unroll
    for (int i = 0; i < 4; i++)
        ldst[i] = (uint32_t)((lrow + i * 32) * 144 + lch * 16);

    // ldmatrix per-lane bases (bytes, stage-relative)
    const uint32_t a_lm =
        (uint32_t)(((wm + ((lane >> 3) & 1) * 8 + (lane & 7)) * 144 +
                    ((lane >> 4) & 1) * 16));
    const uint32_t b_lm = 3 * GST +
        (uint32_t)(((wn + ((lane >> 4) & 1) * 8 + (lane & 7)) * 144 +
                    ((lane >> 3) & 1) * 16));

    float bias0[4], bias1[4];
#pragma unroll
    for (int nt = 0; nt < 4; nt++) {
        int c = bn + wn + nt * 8 + 2 * t;
        bias0[nt] = bias[c];
        bias1[nt] = bias[c + 1];
    }

    float acc[4][4][4];
#pragma unroll
    for (int mt = 0; mt < 4; mt++)
#pragma unroll
        for (int nt = 0; nt < 4; nt++)
#pragma unroll
            for (int r = 0; r < 4; r++) acc[mt][nt][r] = 0.0f;

    const int nk = K / 64;

    // prologue: prefetch stages 0,1 (one commit group per stage)
#pragma unroll
    for (int s = 0; s < 2; s++) {
        const uint32_t dA = sb + (uint32_t)s * GST;
        const uint32_t dB = sb + 3 * GST + (uint32_t)s * GST;
        const int ko = s * 64;
#pragma unroll
        for (int i = 0; i < 4; i++) {
            CP_ASYNC16(dA + ldst[i], Arow + (size_t)(i * 32) * K + ko);
            CP_ASYNC16(dB + ldst[i], Brow + (size_t)(i * 32) * K + ko);
        }
        CP_COMMIT();
    }

    for (int kt = 0; kt < nk; kt++) {
        const int slot = kt % 3;

        CP_WAIT1();              // group kt complete (1 group per iter)
        __syncthreads();         // visibility + slot-recycle ordering

        if (kt + 2 < nk) {
            const int ns = (kt + 2) % 3;
            const uint32_t dA = sb + (uint32_t)ns * GST;
            const uint32_t dB = sb + 3 * GST + (uint32_t)ns * GST;
            const int ko = (kt + 2) * 64;
#pragma unroll
            for (int i = 0; i < 4; i++) {
                CP_ASYNC16(dA + ldst[i], Arow + (size_t)(i * 32) * K + ko);
                CP_ASYNC16(dB + ldst[i], Brow + (size_t)(i * 32) * K + ko);
            }
        }
        CP_COMMIT();             // unconditional: keep group accounting aligned

        const uint32_t aB = sb + (uint32_t)slot * GST + a_lm;
        const uint32_t bB = sb + (uint32_t)slot * GST + b_lm;
#pragma unroll
        for (int c = 0; c < 4; c++) {         // k chunk of 16 halfs
            uint32_t af[4][4], bfr[2][4];
#pragma unroll
            for (int mt = 0; mt < 4; mt++)
                LDM_X4(af[mt], aB + mt * 2304 + c * 32);
#pragma unroll
            for (int ntp = 0; ntp < 2; ntp++)
                LDM_X4(bfr[ntp], bB + ntp * 2304 + c * 32);
#pragma unroll
            for (int mt = 0; mt < 4; mt++)
#pragma unroll
                for (int nt = 0; nt < 4; nt++)
                    mma_f16(acc[mt][nt], af[mt],
                            bfr[nt >> 1][(nt & 1) * 2],
                            bfr[nt >> 1][(nt & 1) * 2 + 1]);
        }
    }

    // epilogue
#pragma unroll
    for (int mt = 0; mt < 4; mt++) {
        const int r0 = bm + wm + mt * 16 + g;
#pragma unroll
        for (int nt = 0; nt < 4; nt++) {
            const int c0 = bn + wn + nt * 8 + 2 * t;
            float v0 = acc[mt][nt][0] + bias0[nt];
            float v1 = acc[mt][nt][1] + bias1[nt];
            float v2 = acc[mt][nt][2] + bias0[nt];
            float v3 = acc[mt][nt][3] + bias1[nt];
            if (HALF_OUT) {
                __half* Ch = (__half*)Cv;
                *(__half2*)(Ch + (size_t)r0 * N + c0) =
                    __float22half2_rn(make_float2(v0, v1));
                *(__half2*)(Ch + (size_t)(r0 + 8) * N + c0) =
                    __float22half2_rn(make_float2(v2, v3));
            } else {
                float* Cf = (float*)Cv;
                *(float2*)(Cf + (size_t)r0 * N + c0)       = make_float2(v0, v1);
                *(float2*)(Cf + (size_t)(r0 + 8) * N + c0) = make_float2(v2, v3);
            }
        }
    }
}

// ===========================================================================
// fp16 tensor-core causal flash attention (R6 structure, exp2-domain softmax).
// Block = (q-tile 64, head, batch), 128 threads = 4 warps, warp = 16 q-rows.
// Q frags in regs; K via ldmatrix; V via ldmatrix.trans; P in registers.
// K/V double-buffered cp.async. One __syncthreads per KV tile.
// smem halfs, row stride 72: Q 9216B; K,V 2 stages each 9216B. Total 46080B.
// ===========================================================================
#define AST   9216
#define ATTN_SMEM (5 * AST)    // 46080

__global__ __launch_bounds__(128) void attn_f16_kernel(
    const __half* __restrict__ qkv, __half* __restrict__ out)
{
    extern __shared__ __half smh[];
    const uint32_t sb = smem_u32(smh);
    // bytes: Q [0,AST), K stage s [AST + s*AST), V stage s [3*AST + s*AST)

    const int qt   = blockIdx.x;
    const int h    = blockIdx.y;
    const int b    = blockIdx.z;
    const int tid  = threadIdx.x;
    const int wid  = tid >> 5;
    const int lane = tid & 31;
    const int g    = lane >> 2;
    const int t    = lane & 3;
    const int r0   = wid * 16;
    const float sl2e = 0.125f * 1.4426950408889634f;   // scale * log2(e)

    // loader mapping: 4 x 16B chunks per thread per 64x64 half tile
    const int lrow = tid >> 3;            // + i*16
    const int lch  = tid & 7;
    uint32_t ldst[4];
#pragma unroll
    for (int i = 0; i < 4; i++)
        ldst[i] = (uint32_t)((lrow + i * 16) * 144 + lch * 16);

    const size_t bq = ((size_t)b * S_LEN + (size_t)qt * 64);
    const __half* Qg = qkv + (bq + lrow) * E3 + h * HDIM + lch * 8;

    // ldmatrix per-lane bases
    const uint32_t k_lm = sb + AST +
        (uint32_t)(((((lane >> 4) & 1) * 8 + (lane & 7)) * 144 +
                    ((lane >> 3) & 1) * 16));
    const uint32_t v_lm = sb + 3 * AST +
        (uint32_t)(((((lane >> 3) & 1) * 8 + (lane & 7)) * 144 +
                    ((lane >> 4) & 1) * 16));

    // prologue: load Q + K0 + V0
    {
        const size_t bk = (size_t)b * S_LEN;   // kt = 0
        const __half* Kg = qkv + (bk + lrow) * E3 + EMB + h * HDIM + lch * 8;
        const __half* Vg = Kg + EMB;
#pragma unroll
        for (int i = 0; i < 4; i++) {
            CP_ASYNC16(sb + ldst[i],           Qg + (size_t)(i * 16) * E3);
            CP_ASYNC16(sb + AST + ldst[i],     Kg + (size_t)(i * 16) * E3);
            CP_ASYNC16(sb + 3 * AST + ldst[i], Vg + (size_t)(i * 16) * E3);
        }
        CP_COMMIT();
        CP_WAIT0();
        __syncthreads();
    }

    // Q fragments (plain conflict-free LDS: bank = 4g+t)
    const uint32_t* Qw = (const uint32_t*)smh;
    uint32_t qf[4][4];
#pragma unroll
    for (int c = 0; c < 4; c++) {
        const uint32_t* p0 = Qw + (r0 + g) * 36 + c * 8 + t;
        const uint32_t* p1 = Qw + (r0 + g + 8) * 36 + c * 8 + t;
        qf[c][0] = p0[0];
        qf[c][1] = p1[0];
        qf[c][2] = p0[4];
        qf[c][3] = p1[4];
    }

    float m_lo = -CUDART_INF_F, m_hi = -CUDART_INF_F;
    float l_lo = 0.0f, l_hi = 0.0f;
    float oacc[8][4];
#pragma unroll
    for (int nt = 0; nt < 8; nt++)
#pragma unroll
        for (int r = 0; r < 4; r++) oacc[nt][r] = 0.0f;

    for (int kt = 0; kt <= qt; kt++) {
        const int cur  = kt & 1;
        const bool more = (kt < qt);

        // prefetch next K/V tile
        if (more) {
            const int nxt = cur ^ 1;
            const size_t bk = (size_t)b * S_LEN + (size_t)(kt + 1) * 64;
            const __half* Kg = qkv + (bk + lrow) * E3 + EMB + h * HDIM + lch * 8;
            const __half* Vg = Kg + EMB;
            const uint32_t dK = sb + AST + (uint32_t)nxt * AST;
            const uint32_t dV = sb + 3 * AST + (uint32_t)nxt * AST;
#pragma unroll
            for (int i = 0; i < 4; i++) {
                CP_ASYNC16(dK + ldst[i], Kg + (size_t)(i * 16) * E3);
                CP_ASYNC16(dV + ldst[i], Vg + (size_t)(i * 16) * E3);
            }
            CP_COMMIT();
        }

        // ---- S = Q K^T (16x64 per warp) ----
        const uint32_t kB = k_lm + (uint32_t)cur * AST;
        float sacc[8][4];
#pragma unroll
        for (int nt = 0; nt < 8; nt++)
#pragma unroll
            for (int r = 0; r < 4; r++) sacc[nt][r] = 0.0f;

#pragma unroll
        for (int c = 0; c < 4; c++) {
#pragma unroll
            for (int ntp = 0; ntp < 4; ntp++) {
                uint32_t bfr[4];
                LDM_X4(bfr, kB + ntp * 2304 + c * 32);
                mma_f16(sacc[2 * ntp + 0], qf[c], bfr[0], bfr[1]);
                mma_f16(sacc[2 * ntp + 1], qf[c], bfr[2], bfr[3]);
            }
        }

        // ---- scale into log2 domain + causal mask (diagonal tile only) ----
        const bool diag = (kt == qt);
#pragma unroll
        for (int nt = 0; nt < 8; nt++) {
            const int c0 = nt * 8 + 2 * t;
#pragma unroll
            for (int r = 0; r < 4; r++) sacc[nt][r] *= sl2e;
            if (diag) {
                const int rlo = r0 + g, rhi = r0 + g + 8;
                if (c0 + 0 > rlo) sacc[nt][0] = -CUDART_INF_F;
                if (c0 + 1 > rlo) sacc[nt][1] = -CUDART_INF_F;
                if (c0 + 0 > rhi) sacc[nt][2] = -CUDART_INF_F;
                if (c0 + 1 > rhi) sacc[nt][3] = -CUDART_INF_F;
            }
        }

        // ---- online softmax (exp2 domain, quad shuffles) ----
        float tmax_lo = -CUDART_INF_F, tmax_hi = -CUDART_INF_F;
#pragma unroll
        for (int nt = 0; nt < 8; nt++) {
            tmax_lo = fmaxf(tmax_lo, fmaxf(sacc[nt][0], sacc[nt][1]));
            tmax_hi = fmaxf(tmax_hi, fmaxf(sacc[nt][2], sacc[nt][3]));
        }
        tmax_lo = fmaxf(tmax_lo, __shfl_xor_sync(0xFFFFFFFF, tmax_lo, 1));
        tmax_lo = fmaxf(tmax_lo, __shfl_xor_sync(0xFFFFFFFF, tmax_lo, 2));
        tmax_hi = fmaxf(tmax_hi, __shfl_xor_sync(0xFFFFFFFF, tmax_hi, 1));
        tmax_hi = fmaxf(tmax_hi, __shfl_xor_sync(0xFFFFFFFF, tmax_hi, 2));

        const float mnew_lo = fmaxf(m_lo, tmax_lo);
        const float mnew_hi = fmaxf(m_hi, tmax_hi);
        const float alpha_lo = exp2f(m_lo - mnew_lo);
        const float alpha_hi = exp2f(m_hi - mnew_hi);

        float sum_lo = 0.0f, sum_hi = 0.0f;
        uint32_t pa[8][2];   // P fragments
#pragma unroll
        for (int nt = 0; nt < 8; nt++) {
            float p0 = exp2f(sacc[nt][0] - mnew_lo);
            float p1 = exp2f(sacc[nt][1] - mnew_lo);
            float p2 = exp2f(sacc[nt][2] - mnew_hi);
            float p3 = exp2f(sacc[nt][3] - mnew_hi);
            sum_lo += p0 + p1;
            sum_hi += p2 + p3;
            pa[nt][0] = h2u(__float22half2_rn(make_float2(p0, p1)));
            pa[nt][1] = h2u(__float22half2_rn(make_float2(p2, p3)));
        }
        sum_lo += __shfl_xor_sync(0xFFFFFFFF, sum_lo, 1);
        sum_lo += __shfl_xor_sync(0xFFFFFFFF, sum_lo, 2);
        sum_hi += __shfl_xor_sync(0xFFFFFFFF, sum_hi, 1);
        sum_hi += __shfl_xor_sync(0xFFFFFFFF, sum_hi, 2);

        l_lo = l_lo * alpha_lo + sum_lo;
        l_hi = l_hi * alpha_hi + sum_hi;
        m_lo = mnew_lo;
        m_hi = mnew_hi;

#pragma unroll
        for (int nt = 0; nt < 8; nt++) {
            oacc[nt][0] *= alpha_lo;
            oacc[nt][1] *= alpha_lo;
            oacc[nt][2] *= alpha_hi;
            oacc[nt][3] *= alpha_hi;
        }

        // ---- O += P V ----
        const uint32_t vB = v_lm + (uint32_t)cur * AST;
#pragma unroll
        for (int c = 0; c < 4; c++) {
            uint32_t af[4] = { pa[2 * c][0], pa[2 * c][1],
                               pa[2 * c + 1][0], pa[2 * c + 1][1] };
#pragma unroll
            for (int ntp = 0; ntp < 4; ntp++) {
                uint32_t bfr[4];
                LDM_X4_T(bfr, vB + c * 2304 + ntp * 32);
                mma_f16(oacc[2 * ntp + 0], af, bfr[0], bfr[1]);
                mma_f16(oacc[2 * ntp + 1], af, bfr[2], bfr[3]);
            }
        }

        if (more) {
            CP_WAIT0();
            __syncthreads();
        }
    }

    // ---- epilogue: normalize + store half ----
    const float inv_lo = 1.0f / l_lo;
    const float inv_hi = 1.0f / l_hi;
    __half* obase = out + bq * EMB + h * HDIM;
    __half* orow0 = obase + (size_t)(r0 + g) * EMB;
    __half* orow1 = obase + (size_t)(r0 + g + 8) * EMB;
#pragma unroll
    for (int nt = 0; nt < 8; nt++) {
        const int c0 = nt * 8 + 2 * t;
        *(__half2*)(orow0 + c0) = __float22half2_rn(
            make_float2(oacc[nt][0] * inv_lo, oacc[nt][1] * inv_lo));
        *(__half2*)(orow1 + c0) = __float22half2_rn(
            make_float2(oacc[nt][2] * inv_hi, oacc[nt][3] * inv_hi));
    }
}

// ===========================================================================
// Launch
// ===========================================================================
extern "C" void kernel_launch(void* const* d_in, const int* in_sizes, int n_in,
                              void* d_out, int out_size)
{
    const float* x     = (const float*)d_in[0];   // [4,2048,1024]
    const float* Wqkv  = (const float*)d_in[1];   // [3072,1024]
    const float* bqkv  = (const float*)d_in[2];   // [3072]
    const float* Wproj = (const float*)d_in[3];   // [1024,1024]
    const float* bproj = (const float*)d_in[4];   // [1024]
    float* out = (float*)d_out;                   // [4,2048,1024]

    __half *hx, *hw1, *hw2, *qkv, *att;
    cudaGetSymbolAddress((void**)&hx,  g_hx);
    cudaGetSymbolAddress((void**)&hw1, g_hw1);
    cudaGetSymbolAddress((void**)&hw2, g_hw2);
    cudaGetSymbolAddress((void**)&qkv, g_qkv);
    cudaGetSymbolAddress((void**)&att, g_att);

    cudaFuncSetAttribute(gemm_f16_nt_bias<1>,
                         cudaFuncAttributeMaxDynamicSharedMemorySize, GEMM_SMEM);
    cudaFuncSetAttribute(gemm_f16_nt_bias<0>,
                         cudaFuncAttributeMaxDynamicSharedMemorySize, GEMM_SMEM);
    cudaFuncSetAttribute(attn_f16_kernel,
                         cudaFuncAttributeMaxDynamicSharedMemorySize, ATTN_SMEM);

    // 0) fp32 -> fp16 conversions
    f32_to_f16<<<(MTOT * EMB / 8 + 255) / 256, 256>>>(x, hx, MTOT * EMB);
    f32_to_f16<<<(E3 * EMB / 8 + 255) / 256, 256>>>(Wqkv, hw1, E3 * EMB);
    f32_to_f16<<<(EMB * EMB / 8 + 255) / 256, 256>>>(Wproj, hw2, EMB * EMB);

    // 1) QKV GEMM (fp16 mma, half out)
    {
        dim3 grid(E3 / 128, MTOT / 128);
        gemm_f16_nt_bias<1><<<grid, 256, GEMM_SMEM>>>(hx, hw1, bqkv, qkv,
                                                      MTOT, E3, EMB);
    }
    // 2) causal flash attention (fp16 tensor cores) -> g_att (half)
    {
        dim3 grid(S_LEN / 64, NHEAD, BATCH);
        attn_f16_kernel<<<grid, 128, ATTN_SMEM>>>(qkv, att);
    }
    // 3) proj GEMM (fp16 mma, float out)
    {
        dim3 grid(EMB / 128, MTOT / 128);
        gemm_f16_nt_bias<0><<<grid, 256, GEMM_SMEM>>>(att, hw2, bproj, out,
                                                      MTOT, EMB, EMB);
    }
}